// round 13
// baseline (speedup 1.0000x reference)
#include <cuda_runtime.h>
#include <cstdint>

#define D     64
#define NMEM  16
#define NHOP  2
#define NREL  200
#define BMAX  4096
#define SMAX  (BMAX * NMEM)   // 65536 slots per hop
#define TM    64              // slots per GEMM tile
#define KS    4               // slots per thread (TM/16)
#define CBLK  32              // histogram/scatter blocks per hop
#define NPERS 444             // persistent gemm blocks (3 per SM x 148)
#define MAXTILES 4096

// smem layout for k_gemm (bytes): double-buffered R and H
#define RB0    0
#define RBYTES (D * D * 4)                    // 16384
#define HB0    (2 * RBYTES)                   // 32768
#define HROWB  256                            // 64 floats per row (skew wraps in-row)
#define HBYTES (TM * HROWB)                   // 16384
#define SOFF   (HB0 + 2 * HBYTES)             // 65536
#define GEMM_SMEM (SOFF + 2 * TM * 4)         // 66048 -> 3 blocks/SM

// ---- persistent scratch (no runtime allocation allowed) ----
__device__ int   g_parthist[NHOP][CBLK][NREL];
__device__ int   g_off   [NHOP][NREL + 1];
__device__ int   g_cursor[NHOP][NREL];
__device__ int   g_slots [NHOP][SMAX];
__device__ float g_Y     [NHOP][SMAX][D];   // Y[slot] = R_{r(slot)} @ h_slot
__device__ float g_Wt    [D * D];           // Wt[j][i] = W[i][j]
__device__ float g_RT    [NREL][D * D];     // RT[r][j*64+i] = R[r][i][j]
__device__ int2  g_tiles [MAXTILES];        // x = base slot, y = hop|r<<1|m<<9
__device__ int   g_ntiles;

// ------------------------------------------------------------------
__device__ __forceinline__ uint32_t smem_u32(const void* p) {
    return (uint32_t)__cvta_generic_to_shared(p);
}
__device__ __forceinline__ void cp16(uint32_t dst, const void* src) {
    asm volatile("cp.async.cg.shared.global [%0], [%1], 16;\n"
                 :: "r"(dst), "l"(src));
}
__device__ __forceinline__ void cp_commit() {
    asm volatile("cp.async.commit_group;\n" ::);
}
template <int N>
__device__ __forceinline__ void cp_wait() {
    asm volatile("cp.async.wait_group %0;\n" :: "n"(N));
}

// packed f32x2 helpers
__device__ __forceinline__ unsigned long long pack2(float v) {
    unsigned long long r;
    asm("mov.b64 %0, {%1, %1};" : "=l"(r) : "f"(v));
    return r;
}
__device__ __forceinline__ void fma2(unsigned long long& d,
                                     unsigned long long a,
                                     unsigned long long b) {
    asm("fma.rn.f32x2 %0, %1, %2, %0;" : "+l"(d) : "l"(a), "l"(b));
}

// ------------------------------------------------------------------
// histogram + R transpose (independent prep work)
__global__ __launch_bounds__(256)
void k_count(const int* __restrict__ mem_r,
             const float* __restrict__ rel, int B)
{
    __shared__ int hist[NREL];
    const int hop   = blockIdx.y;
    const int total = B * NMEM;
    const int chunk = (total + CBLK - 1) / CBLK;
    const int start = blockIdx.x * chunk;

    for (int i = threadIdx.x; i < NREL; i += 256) hist[i] = 0;
    __syncthreads();

    const int* src = mem_r + hop * total;
    {
        int base = start + threadIdx.x * 8;
        if (base + 8 <= start + chunk && start + chunk <= total) {
            int4 v0 = *(const int4*)(src + base);
            int4 v1 = *(const int4*)(src + base + 4);
            atomicAdd(&hist[v0.x], 1); atomicAdd(&hist[v0.y], 1);
            atomicAdd(&hist[v0.z], 1); atomicAdd(&hist[v0.w], 1);
            atomicAdd(&hist[v1.x], 1); atomicAdd(&hist[v1.y], 1);
            atomicAdd(&hist[v1.z], 1); atomicAdd(&hist[v1.w], 1);
        } else {
            for (int k = threadIdx.x * 8; k < threadIdx.x * 8 + 8; ++k)
                if (k < chunk && start + k < total)
                    atomicAdd(&hist[src[start + k]], 1);
        }
    }

    // g_RT[r][j*64+i] = rel[r*4096 + i*64 + j]  (coalesced writes)
    {
        const int nthr = CBLK * NHOP * 256;
        const int gid  = (blockIdx.y * CBLK + blockIdx.x) * 256 + threadIdx.x;
        const int nelem = NREL * D * D;
        for (int w = gid; w < nelem; w += nthr) {
            int r = w >> 12, j = (w >> 6) & 63, i = w & 63;
            ((float*)g_RT)[w] = rel[(r << 12) + (i << 6) + j];
        }
    }
    __syncthreads();

    for (int i = threadIdx.x; i < NREL; i += 256)
        g_parthist[hop][blockIdx.x][i] = hist[i];
}

// sum partials, scan offsets, transpose W, build the flat tile list
__global__ __launch_bounds__(512)
void k_scan(const float* __restrict__ W)
{
    __shared__ int cnt[NHOP * NREL];
    __shared__ int nt [NHOP * NREL];
    __shared__ int toff[NHOP * NREL + 1];
    const int tid = threadIdx.x;

    if (tid < NHOP * NREL) {
        int hop = tid / NREL, r = tid - hop * NREL;
        int s = 0;
        #pragma unroll 8
        for (int b = 0; b < CBLK; ++b) s += g_parthist[hop][b][r];
        cnt[tid] = s;
        nt[tid]  = (s + TM - 1) / TM;
        g_cursor[hop][r] = 0;
    }
    for (int idx = tid; idx < D * D; idx += 512)
        g_Wt[(idx & (D - 1)) * D + (idx >> 6)] = W[idx];
    __syncthreads();

    if (tid < NHOP) {
        int acc = 0;
        for (int r = 0; r < NREL; ++r) {
            g_off[tid][r] = acc; acc += cnt[tid * NREL + r];
        }
        g_off[tid][NREL] = acc;
    }
    if (tid == 0) {
        int acc = 0;
        for (int i = 0; i < NHOP * NREL; ++i) { toff[i] = acc; acc += nt[i]; }
        toff[NHOP * NREL] = acc;
        g_ntiles = acc;
    }
    __syncthreads();

    if (tid < NHOP * NREL) {
        int hop = tid / NREL, r = tid - hop * NREL;
        int n = cnt[tid], base = g_off[hop][r], t0 = toff[tid];
        for (int k = 0; k * TM < n; ++k) {
            int m = n - k * TM; if (m > TM) m = TM;
            int2 e; e.x = base + k * TM; e.y = hop | (r << 1) | (m << 9);
            g_tiles[t0 + k] = e;
        }
    }
}

__global__ __launch_bounds__(256)
void k_scatter(const int* __restrict__ mem_r, int B)
{
    __shared__ int hist[NREL];
    __shared__ int base_s[NREL];
    const int hop   = blockIdx.y;
    const int total = B * NMEM;
    const int chunk = (total + CBLK - 1) / CBLK;
    const int start = blockIdx.x * chunk;

    for (int i = threadIdx.x; i < NREL; i += 256) hist[i] = 0;
    __syncthreads();

    const int* src = mem_r + hop * total;
    int rr[8], lrank[8], idx0 = start + threadIdx.x * 8;
    bool vec = ((chunk & 7) == 0) && (idx0 + 8 <= start + chunk) &&
               (start + chunk <= total);
    if (vec) {
        int4 v0 = *(const int4*)(src + idx0);
        int4 v1 = *(const int4*)(src + idx0 + 4);
        rr[0]=v0.x; rr[1]=v0.y; rr[2]=v0.z; rr[3]=v0.w;
        rr[4]=v1.x; rr[5]=v1.y; rr[6]=v1.z; rr[7]=v1.w;
        #pragma unroll
        for (int t = 0; t < 8; ++t) lrank[t] = atomicAdd(&hist[rr[t]], 1);
    } else {
        #pragma unroll
        for (int t = 0; t < 8; ++t) {
            int k = threadIdx.x * 8 + t;
            rr[t] = -1;
            if (k < chunk && start + k < total) {
                rr[t]    = src[start + k];
                lrank[t] = atomicAdd(&hist[rr[t]], 1);
            }
        }
    }
    __syncthreads();

    for (int i = threadIdx.x; i < NREL; i += 256) {
        int c = hist[i];
        base_s[i] = g_off[hop][i] + (c ? atomicAdd(&g_cursor[hop][i], c) : 0);
    }
    __syncthreads();

    #pragma unroll
    for (int t = 0; t < 8; ++t)
        if (vec || rr[t] >= 0)
            g_slots[hop][base_s[rr[t]] + lrank[t]] = idx0 + t;
}

// ------------------------------------------------------------------
// Persistent pipelined GEMM: 444 blocks walk the flat tile list with
// stride NPERS, double-buffering H (gather) and R (contiguous) via
// cp.async so tile t+1 loads while tile t computes.
__global__ __launch_bounds__(128, 3)
void k_gemm(const int* __restrict__ mem_h,
            const float* __restrict__ entity,
            int B)
{
    const int ntiles = g_ntiles;
    int tl = blockIdx.x;
    if (tl >= ntiles) return;

    extern __shared__ char smem[];
    const uint32_t rb[2] = { smem_u32(smem + RB0),
                             smem_u32(smem + RB0 + RBYTES) };
    const uint32_t hb[2] = { smem_u32(smem + HB0),
                             smem_u32(smem + HB0 + HBYTES) };
    int* sslot = (int*)(smem + SOFF);   // [2][TM]

    const int tid  = threadIdx.x;
    const int ts   = tid >> 3;          // 0..15
    const int ti   = tid & 7;           // 0..7
    const int row  = tid >> 1;          // 0..63 (gather row)
    const int half = tid & 1;           // half-row (128B) per thread

    const int BNM = B * NMEM;
    int rcache[2] = { -1, -1 };

    // prefetch tile `t` into buffer `b`; one commit group per call
    auto prefetch = [&](int t, int b) {
        int2 T = g_tiles[t];
        int hop = T.y & 1, r = (T.y >> 1) & 0xFF, m = T.y >> 9;
        int slot = (row < m) ? g_slots[hop][T.x + row] : -1;
        if (half == 0) sslot[b * TM + row] = slot;
        if (slot >= 0) {
            const char* src = (const char*)
                (entity + (size_t)mem_h[hop * BNM + slot] * D) + half * 128;
            uint32_t rowbase = hb[b] + row * HROWB;
            const uint32_t sk = (row & 7) * 16 + half * 128;
            #pragma unroll
            for (int c = 0; c < 8; ++c)
                cp16(rowbase + ((sk + c * 16) & 255), src + c * 16);
        }
        if (r != rcache[b]) {
            rcache[b] = r;
            const char* Rp = (const char*)&g_RT[r][0];
            #pragma unroll
            for (int c = 0; c < 8; ++c)
                cp16(rb[b] + tid * 128 + c * 16, Rp + tid * 128 + c * 16);
        }
        cp_commit();
    };

    prefetch(tl, 0);
    int buf = 0;

    while (tl < ntiles) {
        const int nxt = tl + NPERS;
        if (nxt < ntiles) { prefetch(nxt, buf ^ 1); cp_wait<1>(); }
        else              { cp_wait<0>(); }
        __syncthreads();   // cur tile's H/R/sslot visible to all warps

        const int hop = g_tiles[tl].y & 1;
        const float4* R4 = (const float4*)(smem + RB0 + buf * RBYTES);
        const float4* H4 = (const float4*)(smem + HB0 + buf * HBYTES);

        unsigned long long acc2[KS][4];
        #pragma unroll
        for (int k = 0; k < KS; ++k)
            #pragma unroll
            for (int p = 0; p < 4; ++p) acc2[k][p] = 0ull;

        #pragma unroll 4
        for (int jq = 0; jq < 16; ++jq) {
            float af[KS][4];
            #pragma unroll
            for (int k = 0; k < KS; ++k) {
                float4 a = H4[(ts + 16 * k) * 16 + (((ts & 7) + jq) & 15)];
                af[k][0] = a.x; af[k][1] = a.y; af[k][2] = a.z; af[k][3] = a.w;
            }
            #pragma unroll
            for (int jj = 0; jj < 4; ++jj) {
                const ulonglong2* bp =
                    (const ulonglong2*)(R4 + (4 * jq + jj) * 16 + ti * 2);
                ulonglong2 t0 = bp[0], t1 = bp[1];
                unsigned long long b2[4] = {t0.x, t0.y, t1.x, t1.y};
                #pragma unroll
                for (int k = 0; k < KS; ++k) {
                    unsigned long long av2 = pack2(af[k][jj]);
                    #pragma unroll
                    for (int p = 0; p < 4; ++p)
                        fma2(acc2[k][p], av2, b2[p]);
                }
            }
        }

        #pragma unroll
        for (int k = 0; k < KS; ++k) {
            int slot = sslot[buf * TM + ts + 16 * k];
            if (slot >= 0) {
                ulonglong2* dst = (ulonglong2*)&g_Y[hop][slot][ti * 8];
                ulonglong2 v0, v1;
                v0.x = acc2[k][0]; v0.y = acc2[k][1];
                v1.x = acc2[k][2]; v1.y = acc2[k][3];
                dst[0] = v0;
                dst[1] = v1;
            }
        }
        __syncthreads();   // buf fully consumed before it is refilled
        tl = nxt; buf ^= 1;
    }
}

// ------------------------------------------------------------------
// Fused epilogue: both hops + score. 2 batch elements per block.
__global__ __launch_bounds__(128)
void k_upd(const int* __restrict__ items,
           const int* __restrict__ mem_t,
           const float* __restrict__ entity,
           float* __restrict__ out,
           int B)
{
    const int tid  = threadIdx.x;
    const int sub  = tid >> 6;
    const int t    = tid & 63;
    const int lane = tid & 31;
    const int warp = tid >> 5;
    const int wH   = warp & 1;
    const int b    = blockIdx.x * 2 + sub;

    __shared__ float item_sv[2][D];
    __shared__ float vbuf[2][D];
    __shared__ float lgs[2][NMEM];
    __shared__ float probs[2][NMEM];
    __shared__ float red[4];

    float item = entity[(size_t)items[b] * D + t];
    float y = 0.0f;

    #pragma unroll
    for (int hop = 0; hop < NHOP; ++hop) {
        item_sv[sub][t] = item;
        __syncthreads();

        #pragma unroll
        for (int s = 0; s < 8; ++s) {
            int m = wH * 8 + s;
            const float* Yp = g_Y[hop][b * NMEM + m];
            float v = Yp[lane] * item_sv[sub][lane] +
                      Yp[lane + 32] * item_sv[sub][lane + 32];
            #pragma unroll
            for (int off = 16; off > 0; off >>= 1)
                v += __shfl_xor_sync(0xffffffffu, v, off);
            if (lane == 0) lgs[sub][m] = v;
        }
        __syncthreads();

        if (t < NMEM) {
            float mx = lgs[sub][0];
            #pragma unroll
            for (int k = 1; k < NMEM; ++k) mx = fmaxf(mx, lgs[sub][k]);
            probs[sub][t] = expf(lgs[sub][t] - mx);
        }
        __syncthreads();

        float denom = 0.0f;
        #pragma unroll
        for (int m = 0; m < NMEM; ++m) denom += probs[sub][m];

        const int* tp = mem_t + (size_t)hop * B * NMEM + b * NMEM;
        float o = 0.0f;
        #pragma unroll
        for (int m = 0; m < NMEM; ++m)
            o = fmaf(probs[sub][m], entity[(size_t)tp[m] * D + t], o);
        o /= denom;

        y += o;
        vbuf[sub][t] = item + o;
        __syncthreads();

        float acc = 0.0f;
        #pragma unroll 8
        for (int j = 0; j < D; ++j)
            acc = fmaf(g_Wt[j * D + t], vbuf[sub][j], acc);
        item = acc;
        __syncthreads();
    }

    float p = item * y;
    #pragma unroll
    for (int off = 16; off > 0; off >>= 1)
        p += __shfl_xor_sync(0xffffffffu, p, off);
    if (lane == 0) red[warp] = p;
    __syncthreads();
    if (tid == 0)  out[b] = red[0] + red[1];
    if (tid == 64) out[b] = red[2] + red[3];
}

// ------------------------------------------------------------------
extern "C" void kernel_launch(void* const* d_in, const int* in_sizes, int n_in,
                              void* d_out, int out_size)
{
    const int*   items  = (const int*)  d_in[0];
    const int*   mem_h  = (const int*)  d_in[1];
    const int*   mem_r  = (const int*)  d_in[2];
    const int*   mem_t  = (const int*)  d_in[3];
    const float* entity = (const float*)d_in[4];
    const float* rel    = (const float*)d_in[5];
    const float* W      = (const float*)d_in[6];
    float*       out    = (float*)d_out;

    const int B = in_sizes[0];   // 4096

    static bool attr_set = false;
    if (!attr_set) {
        cudaFuncSetAttribute(k_gemm, cudaFuncAttributeMaxDynamicSharedMemorySize,
                             GEMM_SMEM);
        attr_set = true;
    }

    k_count  <<<dim3(CBLK, NHOP), 256>>>(mem_r, rel, B);
    k_scan   <<<1, 512>>>(W);
    k_scatter<<<dim3(CBLK, NHOP), 256>>>(mem_r, B);
    k_gemm   <<<NPERS, 128, GEMM_SMEM>>>(mem_h, entity, B);
    k_upd    <<<B / 2, 128>>>(items, mem_t, entity, out, B);
}

// round 14
// speedup vs baseline: 1.3127x; 1.3127x over previous
#include <cuda_runtime.h>
#include <cstdint>

#define D     64
#define NMEM  16
#define NHOP  2
#define NREL  200
#define BMAX  4096
#define SMAX  (BMAX * NMEM)   // 65536 slots per hop
#define TM    96              // slots per GEMM tile (16 ts-groups x 6)
#define KS    6               // slots per thread
#define CBLK  32              // scatter blocks per hop
#define YSPLIT 4              // blocks per bin
#define BINCAP 512            // fixed bin capacity (max count ~420)

// smem layout for k_gemm (bytes): contiguous R + skewed H + slot ids
#define ROFF   0
#define RBYTES (D * D * 4)                    // 16384
#define HOFF   RBYTES
#define HROWB  256                            // 64 floats per row (skew wraps in-row)
#define HBYTES (TM * HROWB)                   // 24576
#define SOFF   (HOFF + HBYTES)
#define GEMM_SMEM (SOFF + TM * 4)             // 41344 -> 5 blocks/SM

// ---- persistent scratch (no runtime allocation allowed) ----
__device__ int   g_cursor[NHOP][NREL];        // zero-init; re-zeroed by k_upd
__device__ int   g_bins  [NHOP][NREL][BINCAP];
__device__ float g_Y     [NHOP][SMAX][D];     // Y[slot] = R_{r(slot)} @ h_slot
__device__ float g_Wt    [D * D];             // Wt[j][i] = W[i][j]
__device__ float g_RT    [NREL][D * D];       // RT[r][j*64+i] = R[r][i][j]

// ------------------------------------------------------------------
__device__ __forceinline__ uint32_t smem_u32(const void* p) {
    return (uint32_t)__cvta_generic_to_shared(p);
}
__device__ __forceinline__ void cp16(uint32_t dst, const void* src) {
    asm volatile("cp.async.cg.shared.global [%0], [%1], 16;\n"
                 :: "r"(dst), "l"(src));
}
__device__ __forceinline__ void cp_commit() {
    asm volatile("cp.async.commit_group;\n" ::);
}
template <int N>
__device__ __forceinline__ void cp_wait() {
    asm volatile("cp.async.wait_group %0;\n" :: "n"(N));
}

// packed f32x2 helpers
__device__ __forceinline__ unsigned long long pack2(float v) {
    unsigned long long r;
    asm("mov.b64 %0, {%1, %1};" : "=l"(r) : "f"(v));
    return r;
}
__device__ __forceinline__ void fma2(unsigned long long& d,
                                     unsigned long long a,
                                     unsigned long long b) {
    asm("fma.rn.f32x2 %0, %1, %2, %0;" : "+l"(d) : "l"(a), "l"(b));
}

// ------------------------------------------------------------------
// ONE prep kernel: scatter slots into fixed-capacity relation bins
// (smem-privatized ranks, ~200 global atomics per block), plus the
// R and W transposes (grid-strided, independent work).
__global__ __launch_bounds__(256)
void k_scatter(const int* __restrict__ mem_r,
               const float* __restrict__ rel,
               const float* __restrict__ W, int B)
{
    __shared__ int hist[NREL];
    __shared__ int base_s[NREL];
    const int hop   = blockIdx.y;
    const int total = B * NMEM;
    const int chunk = (total + CBLK - 1) / CBLK;
    const int start = blockIdx.x * chunk;

    for (int i = threadIdx.x; i < NREL; i += 256) hist[i] = 0;
    __syncthreads();

    const int* src = mem_r + hop * total;
    int rr[8], lrank[8], idx0 = start + threadIdx.x * 8;
    bool vec = ((chunk & 7) == 0) && (idx0 + 8 <= start + chunk) &&
               (start + chunk <= total);
    if (vec) {
        int4 v0 = *(const int4*)(src + idx0);
        int4 v1 = *(const int4*)(src + idx0 + 4);
        rr[0]=v0.x; rr[1]=v0.y; rr[2]=v0.z; rr[3]=v0.w;
        rr[4]=v1.x; rr[5]=v1.y; rr[6]=v1.z; rr[7]=v1.w;
        #pragma unroll
        for (int t = 0; t < 8; ++t) lrank[t] = atomicAdd(&hist[rr[t]], 1);
    } else {
        #pragma unroll
        for (int t = 0; t < 8; ++t) {
            int k = threadIdx.x * 8 + t;
            rr[t] = -1;
            if (k < chunk && start + k < total) {
                rr[t]    = src[start + k];
                lrank[t] = atomicAdd(&hist[rr[t]], 1);
            }
        }
    }
    __syncthreads();

    for (int i = threadIdx.x; i < NREL; i += 256) {
        int c = hist[i];
        base_s[i] = c ? atomicAdd(&g_cursor[hop][i], c) : 0;
    }

    // transposes (independent; overlap the atomic latency)
    {
        const int nthr = CBLK * NHOP * 256;
        const int gid  = (blockIdx.y * CBLK + blockIdx.x) * 256 + threadIdx.x;
        const int nelem = NREL * D * D;
        for (int w = gid; w < nelem; w += nthr) {
            int r = w >> 12, j = (w >> 6) & 63, i = w & 63;
            ((float*)g_RT)[w] = rel[(r << 12) + (i << 6) + j];
        }
        if (gid < D * D)
            g_Wt[(gid & 63) * D + (gid >> 6)] = W[gid];
    }
    __syncthreads();

    #pragma unroll
    for (int t = 0; t < 8; ++t)
        if (vec || rr[t] >= 0)
            g_bins[hop][rr[t]][base_s[rr[t]] + lrank[t]] = idx0 + t;
}

// ------------------------------------------------------------------
// Y[slot] = R @ h_slot. Grid (NREL, YSPLIT, NHOP); block handles tiles
// by, by+YSPLIT, ... of its bin. 41.3KB smem -> 5 blocks/SM.
// Contiguous cp.async R load from g_RT; in-row-skewed H gather;
// packed f32x2 6x8 micro-tile; Y stored as 2 x ulonglong2 per slot.
__global__ __launch_bounds__(128, 5)
void k_gemm(const int* __restrict__ mem_h,
            const float* __restrict__ entity,
            int B)
{
    const int hop  = blockIdx.z;
    const int r    = blockIdx.x;
    const int n    = g_cursor[hop][r];
    const int ntiles = (n + TM - 1) / TM;
    if ((int)blockIdx.y >= ntiles) return;

    extern __shared__ char smem[];
    const uint32_t rbase = smem_u32(smem + ROFF);
    const uint32_t hbase = smem_u32(smem + HOFF);
    int* sslot = (int*)(smem + SOFF);

    const int tid  = threadIdx.x;
    const int ts   = tid >> 3;      // 0..15
    const int ti   = tid & 7;       // 0..7

    const int* __restrict__ bin = &g_bins[hop][r][0];
    const int* __restrict__ mh  = mem_h + (size_t)hop * B * NMEM;

    bool first = true;
    for (int t = blockIdx.y; t < ntiles; t += YSPLIT) {
        if (!first) __syncthreads();   // previous compute done before overwrite

        // gather tile t into H (in-row 16B skew)
        {
            int s = t * TM + tid;
            if (tid < TM) {
                int slot = (s < n) ? bin[s] : -1;
                sslot[tid] = slot;
                if (slot >= 0) {
                    const char* src = (const char*)(entity + (size_t)mh[slot] * D);
                    uint32_t rowbase = hbase + tid * HROWB;
                    const uint32_t sk = (tid & 7) * 16;
                    #pragma unroll
                    for (int c = 0; c < 16; ++c)
                        cp16(rowbase + ((sk + c * 16) & 255), src + c * 16);
                }
            }
            cp_commit();
        }

        if (first) {
            // contiguous async copy of pre-transposed R
            const char* Rp = (const char*)&g_RT[r][0];
            #pragma unroll
            for (int c = 0; c < 8; ++c)
                cp16(rbase + tid * 128 + c * 16, Rp + tid * 128 + c * 16);
            cp_commit();
            first = false;
        }

        cp_wait<0>();
        __syncthreads();

        const float4* R4 = (const float4*)(smem + ROFF);  // RT rows of 16 float4
        const float4* H4 = (const float4*)(smem + HOFF);

        unsigned long long acc2[KS][4];
        #pragma unroll
        for (int k = 0; k < KS; ++k)
            #pragma unroll
            for (int p = 0; p < 4; ++p) acc2[k][p] = 0ull;

        #pragma unroll 2
        for (int jq = 0; jq < 16; ++jq) {
            float af[KS][4];
            #pragma unroll
            for (int k = 0; k < KS; ++k) {
                float4 a = H4[(ts + 16 * k) * 16 + (((ts & 7) + jq) & 15)];
                af[k][0] = a.x; af[k][1] = a.y; af[k][2] = a.z; af[k][3] = a.w;
            }
            #pragma unroll
            for (int jj = 0; jj < 4; ++jj) {
                const ulonglong2* bp =
                    (const ulonglong2*)(R4 + (4 * jq + jj) * 16 + ti * 2);
                ulonglong2 t0 = bp[0], t1 = bp[1];
                unsigned long long b2[4] = {t0.x, t0.y, t1.x, t1.y};
                #pragma unroll
                for (int k = 0; k < KS; ++k) {
                    unsigned long long av2 = pack2(af[k][jj]);
                    #pragma unroll
                    for (int p = 0; p < 4; ++p)
                        fma2(acc2[k][p], av2, b2[p]);
                }
            }
        }

        #pragma unroll
        for (int k = 0; k < KS; ++k) {
            int slot = sslot[ts + 16 * k];
            if (slot >= 0) {
                ulonglong2* dst = (ulonglong2*)&g_Y[hop][slot][ti * 8];
                ulonglong2 v0, v1;
                v0.x = acc2[k][0]; v0.y = acc2[k][1];
                v1.x = acc2[k][2]; v1.y = acc2[k][3];
                dst[0] = v0;
                dst[1] = v1;
            }
        }
    }
}

// ------------------------------------------------------------------
// Fused epilogue: both hops + score. 2 batch elements per block.
// Block 0 also re-zeroes the bin cursors for the next invocation.
__global__ __launch_bounds__(128)
void k_upd(const int* __restrict__ items,
           const int* __restrict__ mem_t,
           const float* __restrict__ entity,
           float* __restrict__ out,
           int B)
{
    const int tid  = threadIdx.x;
    const int sub  = tid >> 6;
    const int t    = tid & 63;
    const int lane = tid & 31;
    const int warp = tid >> 5;
    const int wH   = warp & 1;
    const int b    = blockIdx.x * 2 + sub;

    if (blockIdx.x == 0)
        for (int i = tid; i < NHOP * NREL; i += 128)
            ((int*)g_cursor)[i] = 0;

    __shared__ float item_sv[2][D];
    __shared__ float vbuf[2][D];
    __shared__ float lgs[2][NMEM];
    __shared__ float probs[2][NMEM];
    __shared__ float red[4];

    float item = entity[(size_t)items[b] * D + t];
    float y = 0.0f;

    #pragma unroll
    for (int hop = 0; hop < NHOP; ++hop) {
        item_sv[sub][t] = item;
        __syncthreads();

        #pragma unroll
        for (int s = 0; s < 8; ++s) {
            int m = wH * 8 + s;
            const float* Yp = g_Y[hop][b * NMEM + m];
            float v = Yp[lane] * item_sv[sub][lane] +
                      Yp[lane + 32] * item_sv[sub][lane + 32];
            #pragma unroll
            for (int off = 16; off > 0; off >>= 1)
                v += __shfl_xor_sync(0xffffffffu, v, off);
            if (lane == 0) lgs[sub][m] = v;
        }
        __syncthreads();

        if (t < NMEM) {
            float mx = lgs[sub][0];
            #pragma unroll
            for (int k = 1; k < NMEM; ++k) mx = fmaxf(mx, lgs[sub][k]);
            probs[sub][t] = expf(lgs[sub][t] - mx);
        }
        __syncthreads();

        float denom = 0.0f;
        #pragma unroll
        for (int m = 0; m < NMEM; ++m) denom += probs[sub][m];

        const int* tp = mem_t + (size_t)hop * B * NMEM + b * NMEM;
        float o = 0.0f;
        #pragma unroll
        for (int m = 0; m < NMEM; ++m)
            o = fmaf(probs[sub][m], entity[(size_t)tp[m] * D + t], o);
        o /= denom;

        y += o;
        vbuf[sub][t] = item + o;
        __syncthreads();

        float acc = 0.0f;
        #pragma unroll 8
        for (int j = 0; j < D; ++j)
            acc = fmaf(g_Wt[j * D + t], vbuf[sub][j], acc);
        item = acc;
        __syncthreads();
    }

    float p = item * y;
    #pragma unroll
    for (int off = 16; off > 0; off >>= 1)
        p += __shfl_xor_sync(0xffffffffu, p, off);
    if (lane == 0) red[warp] = p;
    __syncthreads();
    if (tid == 0)  out[b] = red[0] + red[1];
    if (tid == 64) out[b] = red[2] + red[3];
}

// ------------------------------------------------------------------
extern "C" void kernel_launch(void* const* d_in, const int* in_sizes, int n_in,
                              void* d_out, int out_size)
{
    const int*   items  = (const int*)  d_in[0];
    const int*   mem_h  = (const int*)  d_in[1];
    const int*   mem_r  = (const int*)  d_in[2];
    const int*   mem_t  = (const int*)  d_in[3];
    const float* entity = (const float*)d_in[4];
    const float* rel    = (const float*)d_in[5];
    const float* W      = (const float*)d_in[6];
    float*       out    = (float*)d_out;

    const int B = in_sizes[0];   // 4096

    static bool attr_set = false;
    if (!attr_set) {
        cudaFuncSetAttribute(k_gemm, cudaFuncAttributeMaxDynamicSharedMemorySize,
                             GEMM_SMEM);
        attr_set = true;
    }

    k_scatter<<<dim3(CBLK, NHOP), 256>>>(mem_r, rel, W, B);
    k_gemm   <<<dim3(NREL, YSPLIT, NHOP), 128, GEMM_SMEM>>>(mem_h, entity, B);
    k_upd    <<<B / 2, 128>>>(items, mem_t, entity, out, B);
}

// round 15
// speedup vs baseline: 1.7275x; 1.3160x over previous
#include <cuda_runtime.h>
#include <cstdint>

#define D     64
#define NMEM  16
#define NHOP  2
#define NREL  200
#define BMAX  4096
#define SMAX  (BMAX * NMEM)   // 65536 slots per hop
#define TM    112             // slots per GEMM tile (16 ts-groups x 7)
#define KS    7               // slots per thread
#define RPAD  68              // RsT row stride (floats)
#define CBLK  32              // scatter blocks per hop
#define YSPLIT 3              // blocks per bin
#define BINCAP 512            // fixed bin capacity (max count ~420)

// smem layout for k_gemm (bytes) — identical to the 75.8us kernel
#define ROFF   0
#define RBYTES (D * RPAD * 4)                 // 17408
#define HOFF   RBYTES
#define HROWB  256                            // 64 floats per row (skew wraps in-row)
#define HBYTES (TM * HROWB)                   // 28672
#define SOFF   (HOFF + HBYTES)
#define GEMM_SMEM (SOFF + TM * 4)             // 46528 -> 4 blocks/SM

// ---- persistent scratch (no runtime allocation allowed) ----
__device__ int   g_cursor[NHOP][NREL];        // zero-init; re-zeroed by k_upd
__device__ int2  g_bins  [NHOP][NREL][BINCAP];  // {slot, entity_idx}
__device__ float g_Y     [NHOP][SMAX][D];     // Y[slot] = R_{r(slot)} @ h_slot
__device__ float g_Wt    [D * D];             // Wt[j][i] = W[i][j]

// ------------------------------------------------------------------
__device__ __forceinline__ uint32_t smem_u32(const void* p) {
    return (uint32_t)__cvta_generic_to_shared(p);
}
__device__ __forceinline__ void cp16(uint32_t dst, const void* src) {
    asm volatile("cp.async.cg.shared.global [%0], [%1], 16;\n"
                 :: "r"(dst), "l"(src));
}
__device__ __forceinline__ void cp_commit() {
    asm volatile("cp.async.commit_group;\n" ::);
}
template <int N>
__device__ __forceinline__ void cp_wait() {
    asm volatile("cp.async.wait_group %0;\n" :: "n"(N));
}

// packed f32x2 helpers
__device__ __forceinline__ unsigned long long pack2(float v) {
    unsigned long long r;
    asm("mov.b64 %0, {%1, %1};" : "=l"(r) : "f"(v));
    return r;
}
__device__ __forceinline__ void fma2(unsigned long long& d,
                                     unsigned long long a,
                                     unsigned long long b) {
    asm("fma.rn.f32x2 %0, %1, %2, %0;" : "+l"(d) : "l"(a), "l"(b));
}

// ------------------------------------------------------------------
// ONE prep kernel: scatter {slot, entity_idx} into fixed-capacity
// relation bins (smem-privatized ranks), plus the W transpose.
__global__ __launch_bounds__(256)
void k_scatter(const int* __restrict__ mem_r,
               const int* __restrict__ mem_h,
               const float* __restrict__ W, int B)
{
    __shared__ int hist[NREL];
    __shared__ int base_s[NREL];
    const int hop   = blockIdx.y;
    const int total = B * NMEM;
    const int chunk = (total + CBLK - 1) / CBLK;
    const int start = blockIdx.x * chunk;

    for (int i = threadIdx.x; i < NREL; i += 256) hist[i] = 0;
    __syncthreads();

    const int* srcr = mem_r + hop * total;
    const int* srch = mem_h + hop * total;
    int rr[8], hh[8], lrank[8], idx0 = start + threadIdx.x * 8;
    bool vec = ((chunk & 7) == 0) && (idx0 + 8 <= start + chunk) &&
               (start + chunk <= total);
    if (vec) {
        int4 v0 = *(const int4*)(srcr + idx0);
        int4 v1 = *(const int4*)(srcr + idx0 + 4);
        int4 h0 = *(const int4*)(srch + idx0);
        int4 h1 = *(const int4*)(srch + idx0 + 4);
        rr[0]=v0.x; rr[1]=v0.y; rr[2]=v0.z; rr[3]=v0.w;
        rr[4]=v1.x; rr[5]=v1.y; rr[6]=v1.z; rr[7]=v1.w;
        hh[0]=h0.x; hh[1]=h0.y; hh[2]=h0.z; hh[3]=h0.w;
        hh[4]=h1.x; hh[5]=h1.y; hh[6]=h1.z; hh[7]=h1.w;
        #pragma unroll
        for (int t = 0; t < 8; ++t) lrank[t] = atomicAdd(&hist[rr[t]], 1);
    } else {
        #pragma unroll
        for (int t = 0; t < 8; ++t) {
            int k = threadIdx.x * 8 + t;
            rr[t] = -1;
            if (k < chunk && start + k < total) {
                rr[t]    = srcr[start + k];
                hh[t]    = srch[start + k];
                lrank[t] = atomicAdd(&hist[rr[t]], 1);
            }
        }
    }
    __syncthreads();

    for (int i = threadIdx.x; i < NREL; i += 256) {
        int c = hist[i];
        base_s[i] = c ? atomicAdd(&g_cursor[hop][i], c) : 0;
    }

    // W transpose (independent; overlaps the atomic latency)
    {
        const int gid = (blockIdx.y * CBLK + blockIdx.x) * 256 + threadIdx.x;
        if (gid < D * D)
            g_Wt[(gid & 63) * D + (gid >> 6)] = W[gid];
    }
    __syncthreads();

    #pragma unroll
    for (int t = 0; t < 8; ++t)
        if (vec || rr[t] >= 0)
            g_bins[hop][rr[t]][base_s[rr[t]] + lrank[t]] =
                make_int2(idx0 + t, hh[t]);
}

// ------------------------------------------------------------------
// Y[slot] = R @ h_slot. Grid (NREL, YSPLIT, NHOP), 128 threads,
// 7x8 packed f32x2 micro-tile. COALESCED gather: each warp loads two
// entity rows per LDGSTS (16 lanes x 16B per row, index via shfl),
// so one instruction touches 4 cache lines instead of 32.
__global__ __launch_bounds__(128, 4)
void k_gemm(const float* __restrict__ entity,
            const float* __restrict__ rel,
            int B)
{
    const int hop  = blockIdx.z;
    const int r    = blockIdx.x;
    const int n    = g_cursor[hop][r];
    const int ntiles = (n + TM - 1) / TM;
    if ((int)blockIdx.y >= ntiles) return;

    extern __shared__ char smem[];
    float (*RsT)[RPAD] = (float(*)[RPAD])(smem + ROFF);
    const uint32_t hbase = smem_u32(smem + HOFF);
    int* sslot = (int*)(smem + SOFF);

    const int tid   = threadIdx.x;
    const int lane  = tid & 31;
    const int warpi = tid >> 5;
    const int ts    = tid >> 3;     // 0..15
    const int ti    = tid & 7;      // 0..7
    const int rowsW = warpi * 28;   // 28 rows per warp (4*28 = TM)

    const int2* __restrict__ bin = &g_bins[hop][r][0];

    bool first = true;
    for (int t = blockIdx.y; t < ntiles; t += YSPLIT) {
        if (!first) __syncthreads();   // previous compute done before overwrite

        // ---- coalesced gather of tile t ----
        {
            int my_slot = -1, my_e = -1;
            if (lane < 28) {
                int s = t * TM + rowsW + lane;
                if (s < n) { int2 se = bin[s]; my_slot = se.x; my_e = se.y; }
                sslot[rowsW + lane] = my_slot;
            }
            #pragma unroll
            for (int p = 0; p < 14; ++p) {
                int src_lane = 2 * p + (lane >> 4);    // row owner lane
                int e = __shfl_sync(0xffffffffu, my_e, src_lane);
                if (e >= 0) {
                    int row   = rowsW + src_lane;
                    int chunk = lane & 15;
                    const char* src =
                        (const char*)(entity + (size_t)e * D) + chunk * 16;
                    uint32_t dst = hbase + row * HROWB +
                                   (((row & 7) * 16 + chunk * 16) & 255);
                    cp16(dst, src);
                }
            }
            cp_commit();
        }

        if (first) {
            // stage R transposed while the gather is in flight
            const float* __restrict__ Rp = rel + (size_t)r * (D * D);
            for (int idx = tid; idx < D * D; idx += 128) {
                int i = idx >> 6, j = idx & 63;
                RsT[j][i] = Rp[idx];
            }
            first = false;
        }

        cp_wait<0>();
        __syncthreads();   // gather + R visible to all

        const float4* R4 = (const float4*)(smem + ROFF);
        const float4* H4 = (const float4*)(smem + HOFF);

        unsigned long long acc2[KS][4];
        #pragma unroll
        for (int k = 0; k < KS; ++k)
            #pragma unroll
            for (int p = 0; p < 4; ++p) acc2[k][p] = 0ull;

        #pragma unroll 2
        for (int jq = 0; jq < 16; ++jq) {
            float af[KS][4];
            #pragma unroll
            for (int k = 0; k < KS; ++k) {
                // row = ts + 16k (row&7 == ts&7); chunk jq sits at
                // float4 index ((ts&7) + jq) & 15 within the row
                float4 a = H4[(ts + 16 * k) * 16 + (((ts & 7) + jq) & 15)];
                af[k][0] = a.x; af[k][1] = a.y; af[k][2] = a.z; af[k][3] = a.w;
            }
            #pragma unroll
            for (int jj = 0; jj < 4; ++jj) {
                const ulonglong2* bp =
                    (const ulonglong2*)(R4 + (4 * jq + jj) * (RPAD / 4) + ti * 2);
                ulonglong2 t0 = bp[0], t1 = bp[1];
                unsigned long long b2[4] = {t0.x, t0.y, t1.x, t1.y};
                #pragma unroll
                for (int k = 0; k < KS; ++k) {
                    unsigned long long av2 = pack2(af[k][jj]);
                    #pragma unroll
                    for (int p = 0; p < 4; ++p)
                        fma2(acc2[k][p], av2, b2[p]);
                }
            }
        }

        #pragma unroll
        for (int k = 0; k < KS; ++k) {
            int slot = sslot[ts + 16 * k];
            if (slot >= 0) {
                ulonglong2* dst = (ulonglong2*)&g_Y[hop][slot][ti * 8];
                ulonglong2 v0, v1;
                v0.x = acc2[k][0]; v0.y = acc2[k][1];
                v1.x = acc2[k][2]; v1.y = acc2[k][3];
                dst[0] = v0;
                dst[1] = v1;
            }
        }
    }
}

// ------------------------------------------------------------------
// Fused epilogue: both hops + score. 2 batch elements per block.
// Block 0 re-zeroes the bin cursors for the next graph replay.
__global__ __launch_bounds__(128)
void k_upd(const int* __restrict__ items,
           const int* __restrict__ mem_t,
           const float* __restrict__ entity,
           float* __restrict__ out,
           int B)
{
    const int tid  = threadIdx.x;
    const int sub  = tid >> 6;
    const int t    = tid & 63;
    const int lane = tid & 31;
    const int warp = tid >> 5;
    const int wH   = warp & 1;
    const int b    = blockIdx.x * 2 + sub;

    if (blockIdx.x == 0)
        for (int i = tid; i < NHOP * NREL; i += 128)
            ((int*)g_cursor)[i] = 0;

    __shared__ float item_sv[2][D];
    __shared__ float vbuf[2][D];
    __shared__ float lgs[2][NMEM];
    __shared__ float probs[2][NMEM];
    __shared__ float red[4];

    float item = entity[(size_t)items[b] * D + t];
    float y = 0.0f;

    #pragma unroll
    for (int hop = 0; hop < NHOP; ++hop) {
        item_sv[sub][t] = item;
        __syncthreads();

        #pragma unroll
        for (int s = 0; s < 8; ++s) {
            int m = wH * 8 + s;
            const float* Yp = g_Y[hop][b * NMEM + m];
            float v = Yp[lane] * item_sv[sub][lane] +
                      Yp[lane + 32] * item_sv[sub][lane + 32];
            #pragma unroll
            for (int off = 16; off > 0; off >>= 1)
                v += __shfl_xor_sync(0xffffffffu, v, off);
            if (lane == 0) lgs[sub][m] = v;
        }
        __syncthreads();

        if (t < NMEM) {
            float mx = lgs[sub][0];
            #pragma unroll
            for (int k = 1; k < NMEM; ++k) mx = fmaxf(mx, lgs[sub][k]);
            probs[sub][t] = expf(lgs[sub][t] - mx);
        }
        __syncthreads();

        float denom = 0.0f;
        #pragma unroll
        for (int m = 0; m < NMEM; ++m) denom += probs[sub][m];

        const int* tp = mem_t + (size_t)hop * B * NMEM + b * NMEM;
        float o = 0.0f;
        #pragma unroll
        for (int m = 0; m < NMEM; ++m)
            o = fmaf(probs[sub][m], entity[(size_t)tp[m] * D + t], o);
        o /= denom;

        y += o;
        vbuf[sub][t] = item + o;
        __syncthreads();

        float acc = 0.0f;
        #pragma unroll 8
        for (int j = 0; j < D; ++j)
            acc = fmaf(g_Wt[j * D + t], vbuf[sub][j], acc);
        item = acc;
        __syncthreads();
    }

    float p = item * y;
    #pragma unroll
    for (int off = 16; off > 0; off >>= 1)
        p += __shfl_xor_sync(0xffffffffu, p, off);
    if (lane == 0) red[warp] = p;
    __syncthreads();
    if (tid == 0)  out[b] = red[0] + red[1];
    if (tid == 64) out[b] = red[2] + red[3];
}

// ------------------------------------------------------------------
extern "C" void kernel_launch(void* const* d_in, const int* in_sizes, int n_in,
                              void* d_out, int out_size)
{
    const int*   items  = (const int*)  d_in[0];
    const int*   mem_h  = (const int*)  d_in[1];
    const int*   mem_r  = (const int*)  d_in[2];
    const int*   mem_t  = (const int*)  d_in[3];
    const float* entity = (const float*)d_in[4];
    const float* rel    = (const float*)d_in[5];
    const float* W      = (const float*)d_in[6];
    float*       out    = (float*)d_out;

    const int B = in_sizes[0];   // 4096

    static bool attr_set = false;
    if (!attr_set) {
        cudaFuncSetAttribute(k_gemm, cudaFuncAttributeMaxDynamicSharedMemorySize,
                             GEMM_SMEM);
        attr_set = true;
    }

    k_scatter<<<dim3(CBLK, NHOP), 256>>>(mem_r, mem_h, W, B);
    k_gemm   <<<dim3(NREL, YSPLIT, NHOP), 128, GEMM_SMEM>>>(entity, rel, B);
    k_upd    <<<B / 2, 128>>>(items, mem_t, entity, out, B);
}